// round 15
// baseline (speedup 1.0000x reference)
#include <cuda_runtime.h>
#include <math.h>

// Segment sums, zero-initialized at module load; finalize re-zeroes them after
// reading so every graph replay starts from zeros. Sized for B up to 8192.
__device__ float g_pos_sum[8192];
__device__ float g_neg_sum[8192];

// ---------------------------------------------------------------------------
// k1: warp-per-row exp(cosine), lane0 relaxed atomicAdd into per-item segment
//     sums (spread addresses: measured free). No barrier/fence/handshake —
//     warps retire the moment their row is done; the 12800-block launch pool
//     gives dynamic load balancing. Measured ~7.4 TB/s (93% of HBM spec).
//     Swept and rejected: block sizes 128/1024, warp-per-item, persistent
//     grids, 6 in-kernel completion mechanisms, PDL — all measured worse.
//     Block 0 thread 0 zeroes out[0] for finalize's per-block atomics.
// ---------------------------------------------------------------------------
__global__ void __launch_bounds__(256) row_cos_kernel(
    const float* __restrict__ q_pos, const float* __restrict__ i_pos,
    const float* __restrict__ q_neg, const float* __restrict__ i_neg,
    float* __restrict__ out, int pos_rows, int total_rows)
{
    if (blockIdx.x == 0 && threadIdx.x == 0) out[0] = 0.0f;

    const int w = (blockIdx.x * blockDim.x + threadIdx.x) >> 5;
    const int lane = threadIdx.x & 31;
    if (w >= total_rows) return;

    const float4* __restrict__ a4;
    const float4* __restrict__ b4;
    float* __restrict__ dst;
    if (w < pos_rows) {
        a4 = reinterpret_cast<const float4*>(q_pos) + (size_t)w * 256;
        b4 = reinterpret_cast<const float4*>(i_pos) + (size_t)w * 256;
        dst = &g_pos_sum[w >> 1];                  // 2 pos rows per item
    } else {
        const int r = w - pos_rows;
        a4 = reinterpret_cast<const float4*>(q_neg) + (size_t)r * 256;
        b4 = reinterpret_cast<const float4*>(i_neg) + (size_t)r * 256;
        dst = &g_neg_sum[r / 23];                  // 23 neg rows per item
    }

    float dot = 0.0f, na2 = 0.0f, nb2 = 0.0f;
#pragma unroll
    for (int i = 0; i < 8; i++) {
        float4 va = __ldcs(a4 + lane + i * 32);    // stream-once: evict-first
        float4 vb = __ldcs(b4 + lane + i * 32);
        dot = fmaf(va.x, vb.x, dot); na2 = fmaf(va.x, va.x, na2); nb2 = fmaf(vb.x, vb.x, nb2);
        dot = fmaf(va.y, vb.y, dot); na2 = fmaf(va.y, va.y, na2); nb2 = fmaf(vb.y, vb.y, nb2);
        dot = fmaf(va.z, vb.z, dot); na2 = fmaf(va.z, va.z, na2); nb2 = fmaf(vb.z, vb.z, nb2);
        dot = fmaf(va.w, vb.w, dot); na2 = fmaf(va.w, va.w, na2); nb2 = fmaf(vb.w, vb.w, nb2);
    }
#pragma unroll
    for (int off = 16; off > 0; off >>= 1) {
        dot += __shfl_xor_sync(0xffffffffu, dot, off);
        na2 += __shfl_xor_sync(0xffffffffu, na2, off);
        nb2 += __shfl_xor_sync(0xffffffffu, nb2, off);
    }
    if (lane == 0) {
        float denom = fmaxf(sqrtf(na2) * sqrtf(nb2), 1e-8f);
        atomicAdd(dst, expf(dot / denom));         // relaxed, spread: free
    }
}

// ---------------------------------------------------------------------------
// k2: thread-per-item finalize. Reads 2*B floats (32 KB, L2-hot), computes the
//     per-item loss, re-zeroes the segment sums (replay determinism), reduces,
//     one atomicAdd per block into out[0]. Launch-floor bound (~4-5us)
//     regardless of grid size; all in-kernel replacements measured worse.
// ---------------------------------------------------------------------------
__global__ void __launch_bounds__(256) finalize_kernel(float* __restrict__ out, int n_items) {
    __shared__ float red[8];
    const int i = blockIdx.x * blockDim.x + threadIdx.x;

    float loss = 0.0f;
    if (i < n_items) {
        float p = __ldcg(&g_pos_sum[i]);
        float n = __ldcg(&g_neg_sum[i]);
        loss = (n - p) / (p + n + 0.001f);
        g_pos_sum[i] = 0.0f;       // restore scratch for next replay
        g_neg_sum[i] = 0.0f;
    }
#pragma unroll
    for (int off = 16; off > 0; off >>= 1)
        loss += __shfl_xor_sync(0xffffffffu, loss, off);
    if ((threadIdx.x & 31) == 0) red[threadIdx.x >> 5] = loss;
    __syncthreads();
    if (threadIdx.x == 0) {
        float acc = 0.0f;
#pragma unroll
        for (int k = 0; k < 8; k++) acc += red[k];
        atomicAdd(out, acc);
    }
}

// ---------------------------------------------------------------------------
// Inputs (metadata order):
//   0: question_embeddings_pos  [2B, 1024] f32
//   1: question_embeddings_neg  [23B, 1024] f32
//   2: pos_image_embeddings     [2B, 1024] f32
//   3: neg_image_embeddings     [23B, 1024] f32
//   4: batch_size (int scalar)
// Output: f32 scalar.
// ---------------------------------------------------------------------------
extern "C" void kernel_launch(void* const* d_in, const int* in_sizes, int n_in,
                              void* d_out, int out_size) {
    const float* q_pos = (const float*)d_in[0];
    const float* q_neg = (const float*)d_in[1];
    const float* i_pos = (const float*)d_in[2];
    const float* i_neg = (const float*)d_in[3];
    float* out = (float*)d_out;

    const int D = 1024;
    const int B = in_sizes[0] / (2 * D);
    const int pos_rows = 2 * B;
    const int total_rows = 25 * B;

    const int WPB = 8;  // 256 threads / block: best measured configuration
    row_cos_kernel<<<(total_rows + WPB - 1) / WPB, WPB * 32>>>(
        q_pos, i_pos, q_neg, i_neg, out, pos_rows, total_rows);

    finalize_kernel<<<(B + 255) / 256, 256>>>(out, B);
}

// round 16
// speedup vs baseline: 1.0021x; 1.0021x over previous
#include <cuda_runtime.h>
#include <math.h>

// Interleaved per-item segment sums: g_sum[2i] = pos, g_sum[2i+1] = neg.
// Zero-initialized at module load; finalize re-zeroes after reading so every
// graph replay starts from zeros. Sized for B up to 8192.
__device__ float g_sum[2 * 8192];

// ---------------------------------------------------------------------------
// k1: warp-per-row exp(cosine), lane0 relaxed atomicAdd into the interleaved
//     per-item sums (8192 spread addresses: measured free). No barrier/fence/
//     handshake — warps retire the moment their row is done. This streaming
//     shape measured ~7.4 TB/s (93% of HBM spec); every alternative (block
//     128/1024, warp-per-item, persistent, 6 fusion topologies, PDL) worse.
//     Block 0 thread 0 zeroes out[0] for finalize's per-block atomics.
// ---------------------------------------------------------------------------
__global__ void __launch_bounds__(256) row_cos_kernel(
    const float* __restrict__ q_pos, const float* __restrict__ i_pos,
    const float* __restrict__ q_neg, const float* __restrict__ i_neg,
    float* __restrict__ out, int pos_rows, int total_rows)
{
    if (blockIdx.x == 0 && threadIdx.x == 0) out[0] = 0.0f;

    const int w = (blockIdx.x * blockDim.x + threadIdx.x) >> 5;
    const int lane = threadIdx.x & 31;
    if (w >= total_rows) return;

    const float4* __restrict__ a4;
    const float4* __restrict__ b4;
    float* __restrict__ dst;
    if (w < pos_rows) {
        a4 = reinterpret_cast<const float4*>(q_pos) + (size_t)w * 256;
        b4 = reinterpret_cast<const float4*>(i_pos) + (size_t)w * 256;
        dst = &g_sum[(w >> 1) * 2];                // pos slot of item w/2
    } else {
        const int r = w - pos_rows;
        a4 = reinterpret_cast<const float4*>(q_neg) + (size_t)r * 256;
        b4 = reinterpret_cast<const float4*>(i_neg) + (size_t)r * 256;
        dst = &g_sum[(r / 23) * 2 + 1];            // neg slot of item r/23
    }

    float dot = 0.0f, na2 = 0.0f, nb2 = 0.0f;
#pragma unroll
    for (int i = 0; i < 8; i++) {
        float4 va = __ldcs(a4 + lane + i * 32);    // stream-once: evict-first
        float4 vb = __ldcs(b4 + lane + i * 32);
        dot = fmaf(va.x, vb.x, dot); na2 = fmaf(va.x, va.x, na2); nb2 = fmaf(vb.x, vb.x, nb2);
        dot = fmaf(va.y, vb.y, dot); na2 = fmaf(va.y, va.y, na2); nb2 = fmaf(vb.y, vb.y, nb2);
        dot = fmaf(va.z, vb.z, dot); na2 = fmaf(va.z, va.z, na2); nb2 = fmaf(vb.z, vb.z, nb2);
        dot = fmaf(va.w, vb.w, dot); na2 = fmaf(va.w, va.w, na2); nb2 = fmaf(vb.w, vb.w, nb2);
    }
#pragma unroll
    for (int off = 16; off > 0; off >>= 1) {
        dot += __shfl_xor_sync(0xffffffffu, dot, off);
        na2 += __shfl_xor_sync(0xffffffffu, na2, off);
        nb2 += __shfl_xor_sync(0xffffffffu, nb2, off);
    }
    if (lane == 0) {
        float denom = fmaxf(sqrtf(na2) * sqrtf(nb2), 1e-8f);
        atomicAdd(dst, expf(dot / denom));         // relaxed, spread: free
    }
}

// ---------------------------------------------------------------------------
// k2: finalize. Each thread's one float4 load covers TWO items (p,n,p,n) —
//     half the loads/stores of the split-array version. Computes per-item
//     losses, re-zeroes scratch (replay determinism), reduces, one atomicAdd
//     per block into out[0]. Launch-floor bound (~4.5us).
// ---------------------------------------------------------------------------
__global__ void __launch_bounds__(256) finalize_kernel(float* __restrict__ out, int n_pairs4) {
    __shared__ float red[8];
    const int i = blockIdx.x * blockDim.x + threadIdx.x;

    float loss = 0.0f;
    if (i < n_pairs4) {
        float4 v = __ldcg(reinterpret_cast<const float4*>(g_sum) + i);  // p0,n0,p1,n1
        loss  = (v.y - v.x) / (v.x + v.y + 0.001f);
        loss += (v.w - v.z) / (v.z + v.w + 0.001f);
        reinterpret_cast<float4*>(g_sum)[i] = make_float4(0.f, 0.f, 0.f, 0.f);
    }
#pragma unroll
    for (int off = 16; off > 0; off >>= 1)
        loss += __shfl_xor_sync(0xffffffffu, loss, off);
    if ((threadIdx.x & 31) == 0) red[threadIdx.x >> 5] = loss;
    __syncthreads();
    if (threadIdx.x == 0) {
        float acc = 0.0f;
#pragma unroll
        for (int k = 0; k < 8; k++) acc += red[k];
        atomicAdd(out, acc);
    }
}

// ---------------------------------------------------------------------------
// Inputs (metadata order):
//   0: question_embeddings_pos  [2B, 1024] f32
//   1: question_embeddings_neg  [23B, 1024] f32
//   2: pos_image_embeddings     [2B, 1024] f32
//   3: neg_image_embeddings     [23B, 1024] f32
//   4: batch_size (int scalar)
// Output: f32 scalar.
// ---------------------------------------------------------------------------
extern "C" void kernel_launch(void* const* d_in, const int* in_sizes, int n_in,
                              void* d_out, int out_size) {
    const float* q_pos = (const float*)d_in[0];
    const float* q_neg = (const float*)d_in[1];
    const float* i_pos = (const float*)d_in[2];
    const float* i_neg = (const float*)d_in[3];
    float* out = (float*)d_out;

    const int D = 1024;
    const int B = in_sizes[0] / (2 * D);
    const int pos_rows = 2 * B;
    const int total_rows = 25 * B;

    const int WPB = 8;  // 256 threads / block: best measured configuration
    row_cos_kernel<<<(total_rows + WPB - 1) / WPB, WPB * 32>>>(
        q_pos, i_pos, q_neg, i_neg, out, pos_rows, total_rows);

    const int n_pairs4 = B / 2;   // one float4 = 2 items (B=4096 -> 2048)
    finalize_kernel<<<(n_pairs4 + 255) / 256, 256>>>(out, n_pairs4);
}

// round 17
// speedup vs baseline: 1.0163x; 1.0142x over previous
#include <cuda_runtime.h>
#include <math.h>

// Interleaved per-item segment sums: g_sum[2i] = pos, g_sum[2i+1] = neg.
// Zero-initialized at module load; finalize re-zeroes after reading so every
// graph replay starts from zeros. Sized for B up to 8192.
__device__ float g_sum[2 * 8192];

// ---------------------------------------------------------------------------
// k1: warp-per-row exp(cosine), lane0 relaxed atomicAdd into the interleaved
//     per-item sums (8192 spread addresses: measured free). No barrier/fence/
//     handshake — warps retire the moment their row is done.
//     __launch_bounds__(256, 8): cap regs at 32 so 8 blocks fit per SM
//     (64/64 warp slots vs 56/64 at the default regs=36) — more outstanding
//     LDGs per SM to cover the 577-cyc DRAM latency.
//     Block 0 thread 0 zeroes out[0] for finalize's per-block atomics.
// ---------------------------------------------------------------------------
__global__ void __launch_bounds__(256, 8) row_cos_kernel(
    const float* __restrict__ q_pos, const float* __restrict__ i_pos,
    const float* __restrict__ q_neg, const float* __restrict__ i_neg,
    float* __restrict__ out, int pos_rows, int total_rows)
{
    if (blockIdx.x == 0 && threadIdx.x == 0) out[0] = 0.0f;

    const int w = (blockIdx.x * blockDim.x + threadIdx.x) >> 5;
    const int lane = threadIdx.x & 31;
    if (w >= total_rows) return;

    const float4* __restrict__ a4;
    const float4* __restrict__ b4;
    float* __restrict__ dst;
    if (w < pos_rows) {
        a4 = reinterpret_cast<const float4*>(q_pos) + (size_t)w * 256;
        b4 = reinterpret_cast<const float4*>(i_pos) + (size_t)w * 256;
        dst = &g_sum[(w >> 1) * 2];                // pos slot of item w/2
    } else {
        const int r = w - pos_rows;
        a4 = reinterpret_cast<const float4*>(q_neg) + (size_t)r * 256;
        b4 = reinterpret_cast<const float4*>(i_neg) + (size_t)r * 256;
        dst = &g_sum[(r / 23) * 2 + 1];            // neg slot of item r/23
    }

    float dot = 0.0f, na2 = 0.0f, nb2 = 0.0f;
#pragma unroll
    for (int i = 0; i < 8; i++) {
        float4 va = __ldcs(a4 + lane + i * 32);    // stream-once: evict-first
        float4 vb = __ldcs(b4 + lane + i * 32);
        dot = fmaf(va.x, vb.x, dot); na2 = fmaf(va.x, va.x, na2); nb2 = fmaf(vb.x, vb.x, nb2);
        dot = fmaf(va.y, vb.y, dot); na2 = fmaf(va.y, va.y, na2); nb2 = fmaf(vb.y, vb.y, nb2);
        dot = fmaf(va.z, vb.z, dot); na2 = fmaf(va.z, va.z, na2); nb2 = fmaf(vb.z, vb.z, nb2);
        dot = fmaf(va.w, vb.w, dot); na2 = fmaf(va.w, va.w, na2); nb2 = fmaf(vb.w, vb.w, nb2);
    }
#pragma unroll
    for (int off = 16; off > 0; off >>= 1) {
        dot += __shfl_xor_sync(0xffffffffu, dot, off);
        na2 += __shfl_xor_sync(0xffffffffu, na2, off);
        nb2 += __shfl_xor_sync(0xffffffffu, nb2, off);
    }
    if (lane == 0) {
        float denom = fmaxf(sqrtf(na2) * sqrtf(nb2), 1e-8f);
        atomicAdd(dst, expf(dot / denom));         // relaxed, spread: free
    }
}

// ---------------------------------------------------------------------------
// k2: finalize. One float4 load covers TWO items (p,n,p,n). Per-item losses,
//     scratch re-zero (replay determinism), block reduce, one atomicAdd per
//     block into out[0]. Pure launch-floor cost (~4.5us, grid-size invariant).
// ---------------------------------------------------------------------------
__global__ void __launch_bounds__(256) finalize_kernel(float* __restrict__ out, int n_pairs4) {
    __shared__ float red[8];
    const int i = blockIdx.x * blockDim.x + threadIdx.x;

    float loss = 0.0f;
    if (i < n_pairs4) {
        float4 v = __ldcg(reinterpret_cast<const float4*>(g_sum) + i);  // p0,n0,p1,n1
        loss  = (v.y - v.x) / (v.x + v.y + 0.001f);
        loss += (v.w - v.z) / (v.z + v.w + 0.001f);
        reinterpret_cast<float4*>(g_sum)[i] = make_float4(0.f, 0.f, 0.f, 0.f);
    }
#pragma unroll
    for (int off = 16; off > 0; off >>= 1)
        loss += __shfl_xor_sync(0xffffffffu, loss, off);
    if ((threadIdx.x & 31) == 0) red[threadIdx.x >> 5] = loss;
    __syncthreads();
    if (threadIdx.x == 0) {
        float acc = 0.0f;
#pragma unroll
        for (int k = 0; k < 8; k++) acc += red[k];
        atomicAdd(out, acc);
    }
}

// ---------------------------------------------------------------------------
// Inputs (metadata order):
//   0: question_embeddings_pos  [2B, 1024] f32
//   1: question_embeddings_neg  [23B, 1024] f32
//   2: pos_image_embeddings     [2B, 1024] f32
//   3: neg_image_embeddings     [23B, 1024] f32
//   4: batch_size (int scalar)
// Output: f32 scalar.
// ---------------------------------------------------------------------------
extern "C" void kernel_launch(void* const* d_in, const int* in_sizes, int n_in,
                              void* d_out, int out_size) {
    const float* q_pos = (const float*)d_in[0];
    const float* q_neg = (const float*)d_in[1];
    const float* i_pos = (const float*)d_in[2];
    const float* i_neg = (const float*)d_in[3];
    float* out = (float*)d_out;

    const int D = 1024;
    const int B = in_sizes[0] / (2 * D);
    const int pos_rows = 2 * B;
    const int total_rows = 25 * B;

    const int WPB = 8;  // 256 threads / block
    row_cos_kernel<<<(total_rows + WPB - 1) / WPB, WPB * 32>>>(
        q_pos, i_pos, q_neg, i_neg, out, pos_rows, total_rows);

    const int n_pairs4 = B / 2;   // one float4 = 2 items (B=4096 -> 2048)
    finalize_kernel<<<(n_pairs4 + 255) / 256, 256>>>(out, n_pairs4);
}